// round 12
// baseline (speedup 1.0000x reference)
#include <cuda_runtime.h>
#include <cuda_fp16.h>
#include <cuda_fp8.h>
#include <math.h>
#include <stdint.h>

// ---------------------------------------------------------------------------
// PredictorLG fused MLP:  LN -> (GEMM+GELU)x3 -> GEMM(->2) -> log_softmax
// R12: fp8 e4m3 mma.sync m16n8k32. Halves MMA count and L1 bytes (the R11
// binding constraint). Per-layer power-of-2 activation scaling keeps values
// in e4m3 normal range; descale folded into epilogue constants (exact).
// Desync warp groups + 2 CTAs/SM retained from R11.
// ---------------------------------------------------------------------------

#define ROWS_TILE   64
#define NTHREADS    256
#define LD8         400           // padded fp8 activation row stride (bytes)
#define RTOT        262144
#define ROWS_PER_M  131072

#define S1 (384*384)
#define S2 (384*192)
#define S3 (192*96)
#define MOD_STRIDE (S1+S2+S3)
#define OFF_L2 (S1)
#define OFF_L3 (S1+S2)

__device__ __align__(16) unsigned char g_packedW[2 * MOD_STRIDE];

#define GROUP_BAR(wm) \
    asm volatile("bar.sync %0, 128;" :: "r"(1 + (wm)) : "memory")

// ---------------------------------------------------------------------------
// Weight repack: W[k][n] fp32 -> e4m3 pair-kt32 B-fragment layout.
// m16n8k32 B frag: b0: n=lane>>2, k=(lane&3)*4+{0..3}; b1: k+16.
// 16B/lane covers two consecutive kt32 blocks (K=64 per uint4).
//   dst = ((nt*KTP32 + ktp)*32 + lane)*16 + (kt32&1)*8 + reg*4 + i
// ---------------------------------------------------------------------------
__global__ void pack_weights_kernel(const float* __restrict__ W1,
                                    const float* __restrict__ W2,
                                    const float* __restrict__ W3) {
    int idx = blockIdx.x * blockDim.x + threadIdx.x;
    const float* src;
    int K, N, r, m, layerOff;
    if (idx < 2 * S1) {
        m = idx / S1; r = idx % S1; K = 384; N = 384;
        src = W1 + m * S1; layerOff = 0;
    } else if (idx < 2 * (S1 + S2)) {
        int e = idx - 2 * S1;
        m = e / S2; r = e % S2; K = 384; N = 192;
        src = W2 + m * S2; layerOff = OFF_L2;
    } else if (idx < 2 * (S1 + S2 + S3)) {
        int e = idx - 2 * (S1 + S2);
        m = e / S3; r = e % S3; K = 192; N = 96;
        src = W3 + m * S3; layerOff = OFF_L3;
    } else {
        return;
    }
    int k = r / N, n = r % N;
    int kt32 = k >> 5;
    int kk   = k & 31;
    int ktp  = kt32 >> 1;
    int KTP32 = K >> 6;
    int nt   = n >> 3;
    int lane = (n & 7) * 4 + ((kk >> 2) & 3);
    int reg  = kk >> 4;
    int i    = kk & 3;
    size_t dst = (size_t)m * MOD_STRIDE + layerOff +
                 ((size_t)(nt * KTP32 + ktp) * 32 + lane) * 16 +
                 (kt32 & 1) * 8 + reg * 4 + i;
    g_packedW[dst] = __nv_cvt_float_to_fp8(src[k * N + n],
                                           __NV_SATFINITE, __NV_E4M3);
}

// ---------------------------------------------------------------------------
// mma / ldmatrix / convert / gelu helpers
// ---------------------------------------------------------------------------
__device__ __forceinline__ void mma16832(float c[4], const unsigned a[4],
                                         const unsigned b0, const unsigned b1) {
    asm volatile(
        "mma.sync.aligned.m16n8k32.row.col.f32.e4m3.e4m3.f32 "
        "{%0,%1,%2,%3}, {%4,%5,%6,%7}, {%8,%9}, {%0,%1,%2,%3};\n"
        : "+f"(c[0]), "+f"(c[1]), "+f"(c[2]), "+f"(c[3])
        : "r"(a[0]), "r"(a[1]), "r"(a[2]), "r"(a[3]), "r"(b0), "r"(b1));
}

__device__ __forceinline__ void ldmatrix_x4(unsigned r[4], uint32_t addr) {
    asm volatile(
        "ldmatrix.sync.aligned.m8n8.x4.shared.b16 {%0,%1,%2,%3}, [%4];\n"
        : "=r"(r[0]), "=r"(r[1]), "=r"(r[2]), "=r"(r[3])
        : "r"(addr));
}

// pack two f32 -> e4m3x2 (lo in byte0, hi in byte1)
__device__ __forceinline__ unsigned short pack_e4m3(float hi, float lo) {
    unsigned short r;
    asm("cvt.rn.satfinite.e4m3x2.f32 %0, %1, %2;"
        : "=h"(r) : "f"(hi), "f"(lo));
    return r;
}

// 4 packed e4m3 -> 4 floats
__device__ __forceinline__ void fp8x4_to_f32(unsigned v, float f[4]) {
    unsigned short lo = (unsigned short)(v & 0xffff);
    unsigned short hi = (unsigned short)(v >> 16);
    unsigned h2l, h2h;
    asm("cvt.rn.f16x2.e4m3x2 %0, %1;" : "=r"(h2l) : "h"(lo));
    asm("cvt.rn.f16x2.e4m3x2 %0, %1;" : "=r"(h2h) : "h"(hi));
    __half2 a = *(__half2*)&h2l, b = *(__half2*)&h2h;
    f[0] = __half2float(a.x); f[1] = __half2float(a.y);
    f[2] = __half2float(b.x); f[3] = __half2float(b.y);
}

// scaled GELU: returns out_scale * gelu(v); hs = 0.5*out_scale (folded free)
__device__ __forceinline__ float gelu_s(float v, float hs) {
    float u = v * (0.7978845608028654f + 0.0447149985f * v * v);
    float t;
    asm("tanh.approx.f32 %0, %1;" : "=f"(t) : "f"(u));
    float h = hs * v;
    return h + h * t;
}

// ---------------------------------------------------------------------------
// One GEMM layer (group-local): out = s_out*gelu(inv*(in@W) + bias).
// in/out fp8 e4m3 in smem, f32 acc. Warp grid 2(m) x 4(n).
// A via ldmatrix.x4 (16B sub-rows), double-buffered; B pair-kt32 uint4,
// 2-slot prefetch. hs = 0.5*s_out.
// ---------------------------------------------------------------------------
template <int K, int N, int CHUNK>
__device__ __forceinline__ void gemm_layer(const unsigned char* inBuf,
                                           unsigned char* outBuf,
                                           const unsigned char* __restrict__ Wp,
                                           const float* __restrict__ bias,
                                           float inv, float hs) {
    constexpr int NPASS = N / CHUNK;
    constexpr int CW  = CHUNK / 4;
    constexpr int NF  = CW / 8;
    constexpr int KT  = K / 32;      // kt32 steps
    constexpr int KTP = K / 64;      // kt32 pairs

    const int tid  = threadIdx.x;
    const int lane = tid & 31;
    const int wid  = tid >> 5;
    const int wm   = wid & 1;
    const int wn   = wid >> 1;

    uint32_t sA = (uint32_t)__cvta_generic_to_shared(inBuf);
    const int arow = wm * 32 + (lane & 15);
    const uint32_t aBase = sA + (uint32_t)(arow * LD8 + (lane >> 4) * 16);

    const uint4* bb = (const uint4*)Wp;

#pragma unroll
    for (int p = 0; p < NPASS; ++p) {
        float acc[2][NF][4];
#pragma unroll
        for (int mi = 0; mi < 2; ++mi)
#pragma unroll
            for (int nf = 0; nf < NF; ++nf)
#pragma unroll
                for (int q = 0; q < 4; ++q) acc[mi][nf][q] = 0.f;

        const int colbase = p * CHUNK + wn * CW;
        const int ntbase  = colbase >> 3;
        const uint4* bwarp = bb + (size_t)ntbase * KTP * 32 + lane;
        const int cb = colbase + (lane & 3) * 2;

        // bias into regs (overlaps mainloop)
        float bi[NF][2];
#pragma unroll
        for (int nf = 0; nf < NF; ++nf) {
            bi[nf][0] = __ldg(bias + cb + nf * 8);
            bi[nf][1] = __ldg(bias + cb + nf * 8 + 1);
        }

        // B: 2-slot circular pair prefetch
        uint4 bf[2][NF];
#pragma unroll
        for (int nf = 0; nf < NF; ++nf)
            bf[0][nf] = __ldg(bwarp + (size_t)nf * KTP * 32);

        // A: double-buffered fragments (one ldsm.x4 per mi covers k32)
        unsigned a[2][2][4];
        ldmatrix_x4(a[0][0], aBase);
        ldmatrix_x4(a[0][1], aBase + 16 * LD8);

#pragma unroll
        for (int kt = 0; kt < KT; ++kt) {
            const int ktp  = kt >> 1;
            const int acur = kt & 1;
            const int anxt = acur ^ 1;
            const int bcur = ktp & 1;

            if ((kt & 1) == 0 && ktp + 1 < KTP) {
#pragma unroll
                for (int nf = 0; nf < NF; ++nf)
                    bf[bcur ^ 1][nf] =
                        __ldg(bwarp + (size_t)nf * KTP * 32 + (ktp + 1) * 32);
            }
            if (kt + 1 < KT) {
                uint32_t addr1 = aBase + (uint32_t)((kt + 1) * 32);
                ldmatrix_x4(a[anxt][0], addr1);
                ldmatrix_x4(a[anxt][1], addr1 + 16 * LD8);
            }

#pragma unroll
            for (int nf = 0; nf < NF; ++nf) {
                const unsigned w0 = (kt & 1) ? bf[bcur][nf].z : bf[bcur][nf].x;
                const unsigned w1 = (kt & 1) ? bf[bcur][nf].w : bf[bcur][nf].y;
                mma16832(acc[0][nf], a[acur][0], w0, w1);
                mma16832(acc[1][nf], a[acur][1], w0, w1);
            }
        }

        // epilogue: descale + bias + scaled gelu + fp8 store
        const int r0 = wm * 32 + (lane >> 2);
#pragma unroll
        for (int nf = 0; nf < NF; ++nf) {
            const int c = cb + nf * 8;
#pragma unroll
            for (int mi = 0; mi < 2; ++mi) {
                const int row = r0 + mi * 16;
                float g0 = gelu_s(acc[mi][nf][0] * inv + bi[nf][0], hs);
                float g1 = gelu_s(acc[mi][nf][1] * inv + bi[nf][1], hs);
                float g2 = gelu_s(acc[mi][nf][2] * inv + bi[nf][0], hs);
                float g3 = gelu_s(acc[mi][nf][3] * inv + bi[nf][1], hs);
                *(unsigned short*)(outBuf + row * LD8 + c)       = pack_e4m3(g1, g0);
                *(unsigned short*)(outBuf + (row + 8) * LD8 + c) = pack_e4m3(g3, g2);
            }
        }
    }
}

// ---------------------------------------------------------------------------
// Fused kernel — two independent 128-thread pipelines per CTA.
// Scales: LN out x4; h1 x8; h2 x16; h3 x64 (all exact power-of-2 folding).
// ---------------------------------------------------------------------------
__global__ void __launch_bounds__(NTHREADS, 2)
fused_mlp_kernel(const float* __restrict__ x,
                 const float* __restrict__ ln_g,
                 const float* __restrict__ ln_b,
                 const float* __restrict__ b1,
                 const float* __restrict__ b2,
                 const float* __restrict__ b3,
                 const float* __restrict__ W4,
                 const float* __restrict__ b4,
                 float* __restrict__ out) {
    extern __shared__ __align__(16) unsigned char smem_raw[];
    unsigned char* bufA = smem_raw;                    // [64][400] fp8
    unsigned char* bufB = bufA + ROWS_TILE * LD8;      // [64][400] fp8

    const int tid  = threadIdx.x;
    const int lane = tid & 31;
    const int wid  = tid >> 5;
    const int wm   = wid & 1;
    const int wn   = wid >> 1;
    const long row0 = (long)blockIdx.x * ROWS_TILE;
    const int m = (int)(row0 / ROWS_PER_M);

    // ------------------- Stage 0: LayerNorm*4 -> bufA (e4m3), group-local --
    {
        float4 g4[3], bb4[3];
#pragma unroll
        for (int j = 0; j < 3; ++j) {
            float4 g = ((const float4*)(ln_g + m * 384))[j * 32 + lane];
            float4 b = ((const float4*)(ln_b + m * 384))[j * 32 + lane];
            g4[j]  = make_float4(g.x * 4.f, g.y * 4.f, g.z * 4.f, g.w * 4.f);
            bb4[j] = make_float4(b.x * 4.f, b.y * 4.f, b.z * 4.f, b.w * 4.f);
        }
#pragma unroll
        for (int t = 0; t < 8; ++t) {
            const int r = wm * 32 + wn * 8 + t;
            const float4* xr = (const float4*)(x + (row0 + r) * 384);
            float4 v[3];
            float s = 0.f, q = 0.f;
#pragma unroll
            for (int j = 0; j < 3; ++j) {
                v[j] = xr[j * 32 + lane];
                s += v[j].x + v[j].y + v[j].z + v[j].w;
                q += v[j].x * v[j].x + v[j].y * v[j].y +
                     v[j].z * v[j].z + v[j].w * v[j].w;
            }
#pragma unroll
            for (int off = 16; off; off >>= 1) {
                s += __shfl_xor_sync(0xffffffffu, s, off);
                q += __shfl_xor_sync(0xffffffffu, q, off);
            }
            const float mu   = s * (1.0f / 384.0f);
            const float var  = q * (1.0f / 384.0f) - mu * mu;
            const float rinv = rsqrtf(var + 1e-5f);
#pragma unroll
            for (int j = 0; j < 3; ++j) {
                const int c = (j * 32 + lane) * 4;
                float y0 = (v[j].x - mu) * rinv * g4[j].x + bb4[j].x;
                float y1 = (v[j].y - mu) * rinv * g4[j].y + bb4[j].y;
                float y2 = (v[j].z - mu) * rinv * g4[j].z + bb4[j].z;
                float y3 = (v[j].w - mu) * rinv * g4[j].w + bb4[j].w;
                unsigned pk = (unsigned)pack_e4m3(y1, y0)
                            | ((unsigned)pack_e4m3(y3, y2) << 16);
                *(unsigned*)(bufA + r * LD8 + c) = pk;
            }
        }
    }

    const unsigned char* WpBase = g_packedW + (size_t)m * MOD_STRIDE;

    // ------------------- Layer 1: 384->384, in x4 -> out x8 ----------------
    GROUP_BAR(wm);
    gemm_layer<384, 384, 128>(bufA, bufB, WpBase, b1 + m * 384,
                              0.25f, 4.0f);
    // ------------------- Layer 2: 384->192, in x8 -> out x16 ---------------
    GROUP_BAR(wm);
    gemm_layer<384, 192, 96>(bufB, bufA, WpBase + OFF_L2, b2 + m * 192,
                             0.125f, 8.0f);
    // ------------------- Layer 3: 192->96, in x16 -> out x64 ---------------
    GROUP_BAR(wm);
    gemm_layer<192, 96, 96>(bufA, bufB, WpBase + OFF_L3, b3 + m * 96,
                            0.0625f, 32.0f);

    // ------------------- Layer 4: 96 -> 2 + log_softmax (in x64) -----------
    GROUP_BAR(wm);
    {
        const int glt  = wn * 32 + lane;
        const int r    = wm * 32 + (glt >> 2);
        const int part = glt & 3;
        const float* w4 = W4 + m * 192;
        const unsigned char* hrow = bufB + r * LD8;
        float z0 = 0.f, z1 = 0.f;
#pragma unroll
        for (int kk = 0; kk < 6; ++kk) {
            const int k0 = part * 24 + kk * 4;
            unsigned v = *(const unsigned*)(hrow + k0);
            float f[4];
            fp8x4_to_f32(v, f);
#pragma unroll
            for (int j = 0; j < 4; ++j) {
                z0 += f[j] * __ldg(w4 + (k0 + j) * 2);
                z1 += f[j] * __ldg(w4 + (k0 + j) * 2 + 1);
            }
        }
        z0 += __shfl_xor_sync(0xffffffffu, z0, 1);
        z0 += __shfl_xor_sync(0xffffffffu, z0, 2);
        z1 += __shfl_xor_sync(0xffffffffu, z1, 1);
        z1 += __shfl_xor_sync(0xffffffffu, z1, 2);
        if (part == 0) {
            z0 = z0 * 0.015625f + __ldg(b4 + m * 2 + 0);   // /64
            z1 = z1 * 0.015625f + __ldg(b4 + m * 2 + 1);
            const float mx  = fmaxf(z0, z1);
            const float lse = mx + logf(expf(z0 - mx) + expf(z1 - mx));
            float* o = out + (row0 + r) * 2;
            o[0] = z0 - lse;
            o[1] = z1 - lse;
        }
    }
}

// ---------------------------------------------------------------------------
// Launch
// ---------------------------------------------------------------------------
extern "C" void kernel_launch(void* const* d_in, const int* in_sizes, int n_in,
                              void* d_out, int out_size) {
    const float* x    = (const float*)d_in[0];
    const float* ln_g = (const float*)d_in[1];
    const float* ln_b = (const float*)d_in[2];
    const float* W1   = (const float*)d_in[3];
    const float* b1   = (const float*)d_in[4];
    const float* W2   = (const float*)d_in[5];
    const float* b2   = (const float*)d_in[6];
    const float* W3   = (const float*)d_in[7];
    const float* b3   = (const float*)d_in[8];
    const float* W4   = (const float*)d_in[9];
    const float* b4   = (const float*)d_in[10];
    float* out        = (float*)d_out;

    const int packTotal = 2 * MOD_STRIDE;
    pack_weights_kernel<<<(packTotal + 255) / 256, 256>>>(W1, W2, W3);

    const int smem_bytes = 2 * ROWS_TILE * LD8;
    cudaFuncSetAttribute(fused_mlp_kernel,
                         cudaFuncAttributeMaxDynamicSharedMemorySize, smem_bytes);
    fused_mlp_kernel<<<RTOT / ROWS_TILE, NTHREADS, smem_bytes>>>(
        x, ln_g, ln_b, b1, b2, b3, W4, b4, out);
}

// round 13
// speedup vs baseline: 1.0829x; 1.0829x over previous
#include <cuda_runtime.h>
#include <cuda_fp16.h>
#include <math.h>
#include <stdint.h>

// ---------------------------------------------------------------------------
// PredictorLG fused MLP:  LN -> (GEMM+GELU)x3 -> GEMM(->2) -> log_softmax
// R13: R11 (fp16, desync groups) + CHUNK=192 geometry (NF=6) to cut L1
// crossbar bytes ~30% (A-ldsm redundancy 12->8 on L1, 8->4 on L2).
// A single-buffered (R9 showed double-buffer neutral) to fit 128 regs.
// ---------------------------------------------------------------------------

#define ROWS_TILE   64
#define NTHREADS    256
#define LD          392           // padded activation row stride (halfs)
#define RTOT        262144
#define ROWS_PER_M  131072

#define S1 (384*384)
#define S2 (384*192)
#define S3 (192*96)
#define MOD_STRIDE (S1+S2+S3)
#define OFF_L2 (S1)
#define OFF_L3 (S1+S2)

__device__ __align__(16) __half g_packedW[2 * MOD_STRIDE];

#define GROUP_BAR(wm) \
    asm volatile("bar.sync %0, 128;" :: "r"(1 + (wm)) : "memory")

// ---------------------------------------------------------------------------
// Weight repack: W[k][n] fp32 -> fp16 pair-kt B-fragment layout (16B/lane
// covers two consecutive kt):
//   dst = base + ((nt*KTP + ktp)*32 + lane)*8 + (kt&1)*4 + reg*2 + i
//   lane = (n%8)*4 + ((k%8)>>1);  reg = (k>>3)&1;  i = k&1
// ---------------------------------------------------------------------------
__global__ void pack_weights_kernel(const float* __restrict__ W1,
                                    const float* __restrict__ W2,
                                    const float* __restrict__ W3) {
    int idx = blockIdx.x * blockDim.x + threadIdx.x;
    const float* src;
    int K, N, r, m, layerOff;
    if (idx < 2 * S1) {
        m = idx / S1; r = idx % S1; K = 384; N = 384;
        src = W1 + m * S1; layerOff = 0;
    } else if (idx < 2 * (S1 + S2)) {
        int e = idx - 2 * S1;
        m = e / S2; r = e % S2; K = 384; N = 192;
        src = W2 + m * S2; layerOff = OFF_L2;
    } else if (idx < 2 * (S1 + S2 + S3)) {
        int e = idx - 2 * (S1 + S2);
        m = e / S3; r = e % S3; K = 192; N = 96;
        src = W3 + m * S3; layerOff = OFF_L3;
    } else {
        return;
    }
    int k = r / N, n = r % N;
    int kt  = k >> 4;
    int ktp = kt >> 1;
    int KTP = K >> 5;
    int nt  = n >> 3;
    int lane = (n & 7) * 4 + ((k & 7) >> 1);
    int reg  = (k >> 3) & 1;
    int i    = k & 1;
    int dst  = m * MOD_STRIDE + layerOff +
               ((nt * KTP + ktp) * 32 + lane) * 8 + (kt & 1) * 4 + reg * 2 + i;
    g_packedW[dst] = __float2half(src[k * N + n]);
}

// ---------------------------------------------------------------------------
// mma / ldmatrix / gelu helpers
// ---------------------------------------------------------------------------
__device__ __forceinline__ void mma16816(float c[4], const unsigned a[4],
                                         const unsigned b0, const unsigned b1) {
    asm volatile(
        "mma.sync.aligned.m16n8k16.row.col.f32.f16.f16.f32 "
        "{%0,%1,%2,%3}, {%4,%5,%6,%7}, {%8,%9}, {%0,%1,%2,%3};\n"
        : "+f"(c[0]), "+f"(c[1]), "+f"(c[2]), "+f"(c[3])
        : "r"(a[0]), "r"(a[1]), "r"(a[2]), "r"(a[3]), "r"(b0), "r"(b1));
}

__device__ __forceinline__ void ldmatrix_x4(unsigned r[4], uint32_t addr) {
    asm volatile(
        "ldmatrix.sync.aligned.m8n8.x4.shared.b16 {%0,%1,%2,%3}, [%4];\n"
        : "=r"(r[0]), "=r"(r[1]), "=r"(r[2]), "=r"(r[3])
        : "r"(addr));
}

// packed fp16 GELU (tanh approx, HW MUFU.TANH on f16x2)
__device__ __forceinline__ __half2 gelu_h2(__half2 v) {
    const __half2 c0 = __float2half2_rn(0.7978845608f);
    const __half2 c1 = __float2half2_rn(0.044715f);
    const __half2 hf = __float2half2_rn(0.5f);
    __half2 vv = __hmul2(v, v);
    __half2 u  = __hmul2(v, __hfma2(c1, vv, c0));
    unsigned ui = *(unsigned*)&u, ti;
    asm("tanh.approx.f16x2 %0, %1;" : "=r"(ti) : "r"(ui));
    __half2 t  = *(__half2*)&ti;
    __half2 hv = __hmul2(v, hf);
    return __hfma2(hv, t, hv);
}

// ---------------------------------------------------------------------------
// One GEMM layer (group-local, no barriers inside):
// out = gelu(in[64,K] @ W[K,N] + bias), fp16 in/out, f32 acc.
// Warp grid 2(m) x 4(n), CHUNK cols per pass (CW=CHUNK/4 per warp).
// A single-buffered ldmatrix; B pair-kt uint4, 2-slot prefetch.
// ---------------------------------------------------------------------------
template <int K, int N, int CHUNK>
__device__ __forceinline__ void gemm_layer(const __half* inBuf,
                                           __half* outBuf,
                                           const __half* __restrict__ Wp,
                                           const float* __restrict__ bias) {
    constexpr int NPASS = N / CHUNK;
    constexpr int CW  = CHUNK / 4;
    constexpr int NF  = CW / 8;
    constexpr int KT  = K / 16;
    constexpr int KTP = KT / 2;

    const int tid  = threadIdx.x;
    const int lane = tid & 31;
    const int wid  = tid >> 5;
    const int wm   = wid & 1;
    const int wn   = wid >> 1;

    uint32_t sA = (uint32_t)__cvta_generic_to_shared(inBuf);
    const int arow     = wm * 32 + (lane & 15);
    const int acol_off = (lane >> 4) * 8;
    const uint32_t aBase = sA + (uint32_t)((arow * LD + acol_off) * 2);

    const uint4* bb = (const uint4*)Wp;

#pragma unroll
    for (int p = 0; p < NPASS; ++p) {
        float acc[2][NF][4];
#pragma unroll
        for (int mi = 0; mi < 2; ++mi)
#pragma unroll
            for (int nf = 0; nf < NF; ++nf)
#pragma unroll
                for (int q = 0; q < 4; ++q) acc[mi][nf][q] = 0.f;

        const int colbase = p * CHUNK + wn * CW;
        const int ntbase  = colbase >> 3;
        const uint4* bwarp = bb + (size_t)ntbase * KTP * 32 + lane;
        const int cb = colbase + (lane & 3) * 2;

        // bias into regs (overlaps mainloop latency)
        float bi[NF][2];
#pragma unroll
        for (int nf = 0; nf < NF; ++nf) {
            bi[nf][0] = __ldg(bias + cb + nf * 8);
            bi[nf][1] = __ldg(bias + cb + nf * 8 + 1);
        }

        // B: 2-slot circular pair prefetch
        uint4 bf[2][NF];
#pragma unroll
        for (int nf = 0; nf < NF; ++nf)
            bf[0][nf] = __ldg(bwarp + (size_t)nf * KTP * 32);

#pragma unroll
        for (int kt = 0; kt < KT; ++kt) {
            const int ktp  = kt >> 1;
            const int bcur = ktp & 1;

            if ((kt & 1) == 0 && ktp + 1 < KTP) {
#pragma unroll
                for (int nf = 0; nf < NF; ++nf)
                    bf[bcur ^ 1][nf] =
                        __ldg(bwarp + (size_t)nf * KTP * 32 + (ktp + 1) * 32);
            }

            unsigned a[2][4];
            uint32_t addr0 = aBase + (uint32_t)(kt * 32);
            ldmatrix_x4(a[0], addr0);
            ldmatrix_x4(a[1], addr0 + 16 * LD * 2);

#pragma unroll
            for (int nf = 0; nf < NF; ++nf) {
                const unsigned w0 = (kt & 1) ? bf[bcur][nf].z : bf[bcur][nf].x;
                const unsigned w1 = (kt & 1) ? bf[bcur][nf].w : bf[bcur][nf].y;
                mma16816(acc[0][nf], a[0], w0, w1);
                mma16816(acc[1][nf], a[1], w0, w1);
            }
        }

        // epilogue: bias + packed half2 gelu + store
        const int r0 = wm * 32 + (lane >> 2);
#pragma unroll
        for (int nf = 0; nf < NF; ++nf) {
            const int c = cb + nf * 8;
#pragma unroll
            for (int mi = 0; mi < 2; ++mi) {
                const int row = r0 + mi * 16;
                __half2 p01 = __floats2half2_rn(acc[mi][nf][0] + bi[nf][0],
                                                acc[mi][nf][1] + bi[nf][1]);
                __half2 p23 = __floats2half2_rn(acc[mi][nf][2] + bi[nf][0],
                                                acc[mi][nf][3] + bi[nf][1]);
                *(__half2*)(outBuf + row * LD + c)       = gelu_h2(p01);
                *(__half2*)(outBuf + (row + 8) * LD + c) = gelu_h2(p23);
            }
        }
    }
}

// ---------------------------------------------------------------------------
// Fused kernel — two fully independent 128-thread pipelines per CTA.
// ---------------------------------------------------------------------------
__global__ void __launch_bounds__(NTHREADS, 2)
fused_mlp_kernel(const float* __restrict__ x,
                 const float* __restrict__ ln_g,
                 const float* __restrict__ ln_b,
                 const float* __restrict__ b1,
                 const float* __restrict__ b2,
                 const float* __restrict__ b3,
                 const float* __restrict__ W4,
                 const float* __restrict__ b4,
                 float* __restrict__ out) {
    extern __shared__ __align__(16) char smem_raw[];
    __half* bufA = (__half*)smem_raw;                               // [64][392]
    __half* bufB = bufA + ROWS_TILE * LD;                           // [64][392]

    const int tid  = threadIdx.x;
    const int lane = tid & 31;
    const int wid  = tid >> 5;
    const int wm   = wid & 1;
    const int wn   = wid >> 1;
    const long row0 = (long)blockIdx.x * ROWS_TILE;
    const int m = (int)(row0 / ROWS_PER_M);

    // ------------------- Stage 0: LayerNorm -> bufA (fp16), group-local ----
    {
        float4 g4[3], bb4[3];
#pragma unroll
        for (int j = 0; j < 3; ++j) {
            g4[j]  = ((const float4*)(ln_g + m * 384))[j * 32 + lane];
            bb4[j] = ((const float4*)(ln_b + m * 384))[j * 32 + lane];
        }
#pragma unroll
        for (int t = 0; t < 8; ++t) {
            const int r = wm * 32 + wn * 8 + t;
            const float4* xr = (const float4*)(x + (row0 + r) * 384);
            float4 v[3];
            float s = 0.f, q = 0.f;
#pragma unroll
            for (int j = 0; j < 3; ++j) {
                v[j] = xr[j * 32 + lane];
                s += v[j].x + v[j].y + v[j].z + v[j].w;
                q += v[j].x * v[j].x + v[j].y * v[j].y +
                     v[j].z * v[j].z + v[j].w * v[j].w;
            }
#pragma unroll
            for (int off = 16; off; off >>= 1) {
                s += __shfl_xor_sync(0xffffffffu, s, off);
                q += __shfl_xor_sync(0xffffffffu, q, off);
            }
            const float mu   = s * (1.0f / 384.0f);
            const float var  = q * (1.0f / 384.0f) - mu * mu;
            const float rinv = rsqrtf(var + 1e-5f);
#pragma unroll
            for (int j = 0; j < 3; ++j) {
                const int c = (j * 32 + lane) * 4;
                float y0 = (v[j].x - mu) * rinv * g4[j].x + bb4[j].x;
                float y1 = (v[j].y - mu) * rinv * g4[j].y + bb4[j].y;
                float y2 = (v[j].z - mu) * rinv * g4[j].z + bb4[j].z;
                float y3 = (v[j].w - mu) * rinv * g4[j].w + bb4[j].w;
                *(__half2*)(bufA + r * LD + c)     = __floats2half2_rn(y0, y1);
                *(__half2*)(bufA + r * LD + c + 2) = __floats2half2_rn(y2, y3);
            }
        }
    }

    const __half* WpBase = g_packedW + (size_t)m * MOD_STRIDE;

    // ------------------- Layer 1: 384 -> 384 (2 passes of 192) -------------
    GROUP_BAR(wm);
    gemm_layer<384, 384, 192>(bufA, bufB, WpBase, b1 + m * 384);

    // ------------------- Layer 2: 384 -> 192 (1 pass of 192) ---------------
    GROUP_BAR(wm);
    gemm_layer<384, 192, 192>(bufB, bufA, WpBase + OFF_L2, b2 + m * 192);

    // ------------------- Layer 3: 192 -> 96 (1 pass of 96) -----------------
    GROUP_BAR(wm);
    gemm_layer<192, 96, 96>(bufA, bufB, WpBase + OFF_L3, b3 + m * 96);

    // ------------------- Layer 4: 96 -> 2 + log_softmax (group-local) ------
    GROUP_BAR(wm);
    {
        const int glt  = wn * 32 + lane;          // 0..127 within group
        const int r    = wm * 32 + (glt >> 2);    // 32 rows per group
        const int part = glt & 3;
        const float* w4 = W4 + m * 192;
        const __half* hrow = bufB + r * LD;
        float z0 = 0.f, z1 = 0.f;
#pragma unroll
        for (int kk = 0; kk < 12; ++kk) {
            const int k = part * 24 + kk * 2;
            __half2 hv = *(const __half2*)(hrow + k);
            float a0 = __half2float(hv.x);
            float a1 = __half2float(hv.y);
            z0 += a0 * __ldg(w4 + k * 2)       + a1 * __ldg(w4 + (k + 1) * 2);
            z1 += a0 * __ldg(w4 + k * 2 + 1)   + a1 * __ldg(w4 + (k + 1) * 2 + 1);
        }
        z0 += __shfl_xor_sync(0xffffffffu, z0, 1);
        z0 += __shfl_xor_sync(0xffffffffu, z0, 2);
        z1 += __shfl_xor_sync(0xffffffffu, z1, 1);
        z1 += __shfl_xor_sync(0xffffffffu, z1, 2);
        if (part == 0) {
            z0 += __ldg(b4 + m * 2 + 0);
            z1 += __ldg(b4 + m * 2 + 1);
            const float mx  = fmaxf(z0, z1);
            const float lse = mx + logf(expf(z0 - mx) + expf(z1 - mx));
            float* o = out + (row0 + r) * 2;
            o[0] = z0 - lse;
            o[1] = z1 - lse;
        }
    }
}

// ---------------------------------------------------------------------------
// Launch
// ---------------------------------------------------------------------------
extern "C" void kernel_launch(void* const* d_in, const int* in_sizes, int n_in,
                              void* d_out, int out_size) {
    const float* x    = (const float*)d_in[0];
    const float* ln_g = (const float*)d_in[1];
    const float* ln_b = (const float*)d_in[2];
    const float* W1   = (const float*)d_in[3];
    const float* b1   = (const float*)d_in[4];
    const float* W2   = (const float*)d_in[5];
    const float* b2   = (const float*)d_in[6];
    const float* W3   = (const float*)d_in[7];
    const float* b3   = (const float*)d_in[8];
    const float* W4   = (const float*)d_in[9];
    const float* b4   = (const float*)d_in[10];
    float* out        = (float*)d_out;

    const int packTotal = 2 * MOD_STRIDE;
    pack_weights_kernel<<<(packTotal + 255) / 256, 256>>>(W1, W2, W3);

    const int smem_bytes = 2 * ROWS_TILE * LD * (int)sizeof(__half);
    cudaFuncSetAttribute(fused_mlp_kernel,
                         cudaFuncAttributeMaxDynamicSharedMemorySize, smem_bytes);
    fused_mlp_kernel<<<RTOT / ROWS_TILE, NTHREADS, smem_bytes>>>(
        x, ln_g, ln_b, b1, b2, b3, W4, b4, out);
}

// round 14
// speedup vs baseline: 1.1647x; 1.0756x over previous
#include <cuda_runtime.h>
#include <cuda_fp16.h>
#include <math.h>
#include <stdint.h>

// ---------------------------------------------------------------------------
// PredictorLG fused MLP:  LN -> (GEMM+GELU)x3 -> GEMM(->2) -> log_softmax
// R14: minimal-L1-bytes geometry (CHUNK 192/192/96) WITHOUT register spills:
// B fragments loaded as uint2 per single kt (bf[2][NF] = 24 regs at NF=6).
// fp16, desync warp groups, 2 CTAs/SM, single-buffered A.
// ---------------------------------------------------------------------------

#define ROWS_TILE   64
#define NTHREADS    256
#define LD          392           // padded activation row stride (halfs)
#define RTOT        262144
#define ROWS_PER_M  131072

#define S1 (384*384)
#define S2 (384*192)
#define S3 (192*96)
#define MOD_STRIDE (S1+S2+S3)
#define OFF_L2 (S1)
#define OFF_L3 (S1+S2)

__device__ __align__(16) __half g_packedW[2 * MOD_STRIDE];

#define GROUP_BAR(wm) \
    asm volatile("bar.sync %0, 128;" :: "r"(1 + (wm)) : "memory")

// ---------------------------------------------------------------------------
// Weight repack: W[k][n] fp32 -> fp16 B-fragment layout, single-kt granules:
//   dst = base + ((nt*KT + kt)*32 + lane)*4 + reg*2 + i   (8B per lane per kt)
//   lane = (n%8)*4 + ((k%8)>>1);  reg = (k>>3)&1;  i = k&1
// ---------------------------------------------------------------------------
__global__ void pack_weights_kernel(const float* __restrict__ W1,
                                    const float* __restrict__ W2,
                                    const float* __restrict__ W3) {
    int idx = blockIdx.x * blockDim.x + threadIdx.x;
    const float* src;
    int K, N, r, m, layerOff;
    if (idx < 2 * S1) {
        m = idx / S1; r = idx % S1; K = 384; N = 384;
        src = W1 + m * S1; layerOff = 0;
    } else if (idx < 2 * (S1 + S2)) {
        int e = idx - 2 * S1;
        m = e / S2; r = e % S2; K = 384; N = 192;
        src = W2 + m * S2; layerOff = OFF_L2;
    } else if (idx < 2 * (S1 + S2 + S3)) {
        int e = idx - 2 * (S1 + S2);
        m = e / S3; r = e % S3; K = 192; N = 96;
        src = W3 + m * S3; layerOff = OFF_L3;
    } else {
        return;
    }
    int k = r / N, n = r % N;
    int kt  = k >> 4;
    int KT  = K >> 4;
    int nt  = n >> 3;
    int lane = (n & 7) * 4 + ((k & 7) >> 1);
    int reg  = (k >> 3) & 1;
    int i    = k & 1;
    int dst  = m * MOD_STRIDE + layerOff +
               ((nt * KT + kt) * 32 + lane) * 4 + reg * 2 + i;
    g_packedW[dst] = __float2half(src[k * N + n]);
}

// ---------------------------------------------------------------------------
// mma / ldmatrix / gelu helpers
// ---------------------------------------------------------------------------
__device__ __forceinline__ void mma16816(float c[4], const unsigned a[4],
                                         const unsigned b0, const unsigned b1) {
    asm volatile(
        "mma.sync.aligned.m16n8k16.row.col.f32.f16.f16.f32 "
        "{%0,%1,%2,%3}, {%4,%5,%6,%7}, {%8,%9}, {%0,%1,%2,%3};\n"
        : "+f"(c[0]), "+f"(c[1]), "+f"(c[2]), "+f"(c[3])
        : "r"(a[0]), "r"(a[1]), "r"(a[2]), "r"(a[3]), "r"(b0), "r"(b1));
}

__device__ __forceinline__ void ldmatrix_x4(unsigned r[4], uint32_t addr) {
    asm volatile(
        "ldmatrix.sync.aligned.m8n8.x4.shared.b16 {%0,%1,%2,%3}, [%4];\n"
        : "=r"(r[0]), "=r"(r[1]), "=r"(r[2]), "=r"(r[3])
        : "r"(addr));
}

// packed fp16 GELU (tanh approx, HW MUFU.TANH on f16x2)
__device__ __forceinline__ __half2 gelu_h2(__half2 v) {
    const __half2 c0 = __float2half2_rn(0.7978845608f);
    const __half2 c1 = __float2half2_rn(0.044715f);
    const __half2 hf = __float2half2_rn(0.5f);
    __half2 vv = __hmul2(v, v);
    __half2 u  = __hmul2(v, __hfma2(c1, vv, c0));
    unsigned ui = *(unsigned*)&u, ti;
    asm("tanh.approx.f16x2 %0, %1;" : "=r"(ti) : "r"(ui));
    __half2 t  = *(__half2*)&ti;
    __half2 hv = __hmul2(v, hf);
    return __hfma2(hv, t, hv);
}

// ---------------------------------------------------------------------------
// One GEMM layer (group-local): out = gelu(in[64,K] @ W[K,N] + bias).
// Warp grid 2(m) x 4(n), CHUNK cols/pass. A single-buffered ldmatrix;
// B single-kt uint2 loads, 2-slot circular prefetch (low reg cost).
// ---------------------------------------------------------------------------
template <int K, int N, int CHUNK>
__device__ __forceinline__ void gemm_layer(const __half* inBuf,
                                           __half* outBuf,
                                           const __half* __restrict__ Wp,
                                           const float* __restrict__ bias) {
    constexpr int NPASS = N / CHUNK;
    constexpr int CW  = CHUNK / 4;
    constexpr int NF  = CW / 8;
    constexpr int KT  = K / 16;

    const int tid  = threadIdx.x;
    const int lane = tid & 31;
    const int wid  = tid >> 5;
    const int wm   = wid & 1;
    const int wn   = wid >> 1;

    uint32_t sA = (uint32_t)__cvta_generic_to_shared(inBuf);
    const int arow     = wm * 32 + (lane & 15);
    const int acol_off = (lane >> 4) * 8;
    const uint32_t aBase = sA + (uint32_t)((arow * LD + acol_off) * 2);

    const uint2* bb = (const uint2*)Wp;

#pragma unroll
    for (int p = 0; p < NPASS; ++p) {
        float acc[2][NF][4];
#pragma unroll
        for (int mi = 0; mi < 2; ++mi)
#pragma unroll
            for (int nf = 0; nf < NF; ++nf)
#pragma unroll
                for (int q = 0; q < 4; ++q) acc[mi][nf][q] = 0.f;

        const int colbase = p * CHUNK + wn * CW;
        const int ntbase  = colbase >> 3;
        const uint2* bwarp = bb + (size_t)ntbase * KT * 32 + lane;
        const int cb = colbase + (lane & 3) * 2;

        // bias into regs
        float bi[NF][2];
#pragma unroll
        for (int nf = 0; nf < NF; ++nf) {
            bi[nf][0] = __ldg(bias + cb + nf * 8);
            bi[nf][1] = __ldg(bias + cb + nf * 8 + 1);
        }

        // B: 2-slot circular single-kt prefetch (uint2 = 8B/lane)
        uint2 bf[2][NF];
#pragma unroll
        for (int nf = 0; nf < NF; ++nf)
            bf[0][nf] = __ldg(bwarp + (size_t)nf * KT * 32);

#pragma unroll
        for (int kt = 0; kt < KT; ++kt) {
            const int cur = kt & 1;
            if (kt + 1 < KT) {
#pragma unroll
                for (int nf = 0; nf < NF; ++nf)
                    bf[cur ^ 1][nf] =
                        __ldg(bwarp + (size_t)nf * KT * 32 + (kt + 1) * 32);
            }

            unsigned a[2][4];
            uint32_t addr0 = aBase + (uint32_t)(kt * 32);
            ldmatrix_x4(a[0], addr0);
            ldmatrix_x4(a[1], addr0 + 16 * LD * 2);

#pragma unroll
            for (int nf = 0; nf < NF; ++nf) {
                mma16816(acc[0][nf], a[0], bf[cur][nf].x, bf[cur][nf].y);
                mma16816(acc[1][nf], a[1], bf[cur][nf].x, bf[cur][nf].y);
            }
        }

        // epilogue: bias + packed half2 gelu + store
        const int r0 = wm * 32 + (lane >> 2);
#pragma unroll
        for (int nf = 0; nf < NF; ++nf) {
            const int c = cb + nf * 8;
#pragma unroll
            for (int mi = 0; mi < 2; ++mi) {
                const int row = r0 + mi * 16;
                __half2 p01 = __floats2half2_rn(acc[mi][nf][0] + bi[nf][0],
                                                acc[mi][nf][1] + bi[nf][1]);
                __half2 p23 = __floats2half2_rn(acc[mi][nf][2] + bi[nf][0],
                                                acc[mi][nf][3] + bi[nf][1]);
                *(__half2*)(outBuf + row * LD + c)       = gelu_h2(p01);
                *(__half2*)(outBuf + (row + 8) * LD + c) = gelu_h2(p23);
            }
        }
    }
}

// ---------------------------------------------------------------------------
// Fused kernel — two fully independent 128-thread pipelines per CTA.
// ---------------------------------------------------------------------------
__global__ void __launch_bounds__(NTHREADS, 2)
fused_mlp_kernel(const float* __restrict__ x,
                 const float* __restrict__ ln_g,
                 const float* __restrict__ ln_b,
                 const float* __restrict__ b1,
                 const float* __restrict__ b2,
                 const float* __restrict__ b3,
                 const float* __restrict__ W4,
                 const float* __restrict__ b4,
                 float* __restrict__ out) {
    extern __shared__ __align__(16) char smem_raw[];
    __half* bufA = (__half*)smem_raw;                               // [64][392]
    __half* bufB = bufA + ROWS_TILE * LD;                           // [64][392]

    const int tid  = threadIdx.x;
    const int lane = tid & 31;
    const int wid  = tid >> 5;
    const int wm   = wid & 1;
    const int wn   = wid >> 1;
    const long row0 = (long)blockIdx.x * ROWS_TILE;
    const int m = (int)(row0 / ROWS_PER_M);

    // ------------------- Stage 0: LayerNorm -> bufA (fp16), group-local ----
    {
        float4 g4[3], bb4[3];
#pragma unroll
        for (int j = 0; j < 3; ++j) {
            g4[j]  = ((const float4*)(ln_g + m * 384))[j * 32 + lane];
            bb4[j] = ((const float4*)(ln_b + m * 384))[j * 32 + lane];
        }
#pragma unroll
        for (int t = 0; t < 8; ++t) {
            const int r = wm * 32 + wn * 8 + t;
            const float4* xr = (const float4*)(x + (row0 + r) * 384);
            float4 v[3];
            float s = 0.f, q = 0.f;
#pragma unroll
            for (int j = 0; j < 3; ++j) {
                v[j] = xr[j * 32 + lane];
                s += v[j].x + v[j].y + v[j].z + v[j].w;
                q += v[j].x * v[j].x + v[j].y * v[j].y +
                     v[j].z * v[j].z + v[j].w * v[j].w;
            }
#pragma unroll
            for (int off = 16; off; off >>= 1) {
                s += __shfl_xor_sync(0xffffffffu, s, off);
                q += __shfl_xor_sync(0xffffffffu, q, off);
            }
            const float mu   = s * (1.0f / 384.0f);
            const float var  = q * (1.0f / 384.0f) - mu * mu;
            const float rinv = rsqrtf(var + 1e-5f);
#pragma unroll
            for (int j = 0; j < 3; ++j) {
                const int c = (j * 32 + lane) * 4;
                float y0 = (v[j].x - mu) * rinv * g4[j].x + bb4[j].x;
                float y1 = (v[j].y - mu) * rinv * g4[j].y + bb4[j].y;
                float y2 = (v[j].z - mu) * rinv * g4[j].z + bb4[j].z;
                float y3 = (v[j].w - mu) * rinv * g4[j].w + bb4[j].w;
                *(__half2*)(bufA + r * LD + c)     = __floats2half2_rn(y0, y1);
                *(__half2*)(bufA + r * LD + c + 2) = __floats2half2_rn(y2, y3);
            }
        }
    }

    const __half* WpBase = g_packedW + (size_t)m * MOD_STRIDE;

    // ------------------- Layer 1: 384 -> 384 (2 passes of 192) -------------
    GROUP_BAR(wm);
    gemm_layer<384, 384, 192>(bufA, bufB, WpBase, b1 + m * 384);

    // ------------------- Layer 2: 384 -> 192 (1 pass of 192) ---------------
    GROUP_BAR(wm);
    gemm_layer<384, 192, 192>(bufB, bufA, WpBase + OFF_L2, b2 + m * 192);

    // ------------------- Layer 3: 192 -> 96 (1 pass of 96) -----------------
    GROUP_BAR(wm);
    gemm_layer<192, 96, 96>(bufA, bufB, WpBase + OFF_L3, b3 + m * 96);

    // ------------------- Layer 4: 96 -> 2 + log_softmax (group-local) ------
    GROUP_BAR(wm);
    {
        const int glt  = wn * 32 + lane;          // 0..127 within group
        const int r    = wm * 32 + (glt >> 2);    // 32 rows per group
        const int part = glt & 3;
        const float* w4 = W4 + m * 192;
        const __half* hrow = bufB + r * LD;
        float z0 = 0.f, z1 = 0.f;
#pragma unroll
        for (int kk = 0; kk < 12; ++kk) {
            const int k = part * 24 + kk * 2;
            __half2 hv = *(const __half2*)(hrow + k);
            float a0 = __half2float(hv.x);
            float a1 = __half2float(hv.y);
            z0 += a0 * __ldg(w4 + k * 2)       + a1 * __ldg(w4 + (k + 1) * 2);
            z1 += a0 * __ldg(w4 + k * 2 + 1)   + a1 * __ldg(w4 + (k + 1) * 2 + 1);
        }
        z0 += __shfl_xor_sync(0xffffffffu, z0, 1);
        z0 += __shfl_xor_sync(0xffffffffu, z0, 2);
        z1 += __shfl_xor_sync(0xffffffffu, z1, 1);
        z1 += __shfl_xor_sync(0xffffffffu, z1, 2);
        if (part == 0) {
            z0 += __ldg(b4 + m * 2 + 0);
            z1 += __ldg(b4 + m * 2 + 1);
            const float mx  = fmaxf(z0, z1);
            const float lse = mx + logf(expf(z0 - mx) + expf(z1 - mx));
            float* o = out + (row0 + r) * 2;
            o[0] = z0 - lse;
            o[1] = z1 - lse;
        }
    }
}

// ---------------------------------------------------------------------------
// Launch
// ---------------------------------------------------------------------------
extern "C" void kernel_launch(void* const* d_in, const int* in_sizes, int n_in,
                              void* d_out, int out_size) {
    const float* x    = (const float*)d_in[0];
    const float* ln_g = (const float*)d_in[1];
    const float* ln_b = (const float*)d_in[2];
    const float* W1   = (const float*)d_in[3];
    const float* b1   = (const float*)d_in[4];
    const float* W2   = (const float*)d_in[5];
    const float* b2   = (const float*)d_in[6];
    const float* W3   = (const float*)d_in[7];
    const float* b3   = (const float*)d_in[8];
    const float* W4   = (const float*)d_in[9];
    const float* b4   = (const float*)d_in[10];
    float* out        = (float*)d_out;

    const int packTotal = 2 * MOD_STRIDE;
    pack_weights_kernel<<<(packTotal + 255) / 256, 256>>>(W1, W2, W3);

    const int smem_bytes = 2 * ROWS_TILE * LD * (int)sizeof(__half);
    cudaFuncSetAttribute(fused_mlp_kernel,
                         cudaFuncAttributeMaxDynamicSharedMemorySize, smem_bytes);
    fused_mlp_kernel<<<RTOT / ROWS_TILE, NTHREADS, smem_bytes>>>(
        x, ln_g, ln_b, b1, b2, b3, W4, b4, out);
}